// round 14
// baseline (speedup 1.0000x reference)
#include <cuda_runtime.h>
#include <math.h>
#include <stdint.h>

#define BATCH 4
#define SEQ   2048
#define DIMN  1024
#define NH    8
#define HD    128
#define MROWS (BATCH*SEQ)   // 8192

// ---------------- scratch (device globals; no runtime allocation) ----------------
__device__ float g_wgate[(size_t)MROWS*DIMN];          // Wgate
__device__ float g_xy[(size_t)MROWS*DIMN];             // X (per-head proj) then Y (groupnorm out)
__device__ float g_sr[(size_t)MROWS*DIMN];             // Sq (suffix scan) then retention out
__device__ float g_colscale[(size_t)BATCH*NH*SEQ];     // per-column scale

__device__ __forceinline__ float swishf(float x) { return x / (1.0f + expf(-x)); }

__device__ __forceinline__ uint32_t f2tf32(float x) {
    uint32_t y;
    asm("cvt.rna.tf32.f32 %0, %1;" : "=r"(y) : "f"(x));
    return y;
}

// D += A*B, m16n8k8 tf32, fp32 accumulate
__device__ __forceinline__ void mma8(float* d, uint32_t a0, uint32_t a1, uint32_t a2, uint32_t a3,
                                     uint32_t b0, uint32_t b1) {
    asm volatile("mma.sync.aligned.m16n8k8.row.col.f32.tf32.tf32.f32 "
                 "{%0,%1,%2,%3},{%4,%5,%6,%7},{%8,%9},{%0,%1,%2,%3};"
                 : "+f"(d[0]), "+f"(d[1]), "+f"(d[2]), "+f"(d[3])
                 : "r"(a0), "r"(a1), "r"(a2), "r"(a3), "r"(b0), "r"(b1));
}

// ---- fragment-major smem packing --------------------------------------------
// A-frag (m16k8): consumer lane reads 4 regs with ONE LDS.128 at blk*132 + lane*4.
//   element (r, c):  blk = (r>>4)*K8CNT + (c>>3)
//                    word = blk*132 + ((r&7)*4 + (c&3))*4 + ((r>>3)&1) + (((c>>2)&1)<<1)
// B-frag (k8n8):  consumer lane reads 2 regs with ONE LDS.64 at blk*66 + lane*2.
//   element (k, n):  blk = (n>>3)*K8CNT + (k>>3)
//                    word = blk*66 + ((n&7)*4 + (k&3))*2 + ((k>>2)&1)
#define AFRAG_W(r, c, K8CNT) \
    ((((r) >> 4) * (K8CNT) + ((c) >> 3)) * 132 + (((r) & 7) * 4 + ((c) & 3)) * 4 \
     + (((r) >> 3) & 1) + (((((c) >> 2) & 1)) << 1))
#define BFRAG_W(k, n, K8CNT) \
    ((((n) >> 3) * (K8CNT) + ((k) >> 3)) * 66 + (((n) & 7) * 4 + ((k) & 3)) * 2 \
     + (((k) >> 2) & 1))

// =================================================================================
// TF32 tensor-core SGEMM, fragment-major smem, double-buffered (1 sync / k-tile).
// C = epi(A (⊙A2) @ B + bias). 128x128 block, 8 warps, warp tile 32x64. K mult 32.
// =================================================================================
#define GA_WORDS (32 * 132)   // 8 mTiles x 4 k8
#define GB_WORDS (64 * 66)    // 16 nTiles x 4 k8
#define GEMM_SMEM (2 * (GA_WORDS + GB_WORDS) * 4)

template<bool SWISH, bool AMUL>
__global__ __launch_bounds__(256)
void sgemm_tf32(const float* __restrict__ A, const float* __restrict__ A2,
                const float* __restrict__ Bm, const float* __restrict__ bias,
                float* __restrict__ C, int K, int N)
{
    extern __shared__ uint32_t smg[];
    uint32_t* As[2] = { smg, smg + GA_WORDS };
    uint32_t* Bs[2] = { smg + 2 * GA_WORDS, smg + 2 * GA_WORDS + GB_WORDS };
    const int tid = threadIdx.x;
    const int warp = tid >> 5, lane = tid & 31;
    const int wr = warp >> 1, wc = warp & 1;
    const int lr = lane >> 2, lc = lane & 3;
    const int rowBase = blockIdx.y * 128;
    const int colBase = blockIdx.x * 128;
    const int aR = tid >> 3, aC = (tid & 7) << 2;

    float acc[2][8][4];
    #pragma unroll
    for (int mt = 0; mt < 2; ++mt)
        #pragma unroll
        for (int nt = 0; nt < 8; ++nt)
            #pragma unroll
            for (int i = 0; i < 4; ++i) acc[mt][nt][i] = 0.0f;

    float4 ra[4], rb[4];
    auto loadTiles = [&](int k0) {
        #pragma unroll
        for (int q4 = 0; q4 < 4; ++q4) {
            int r = aR + q4 * 32;
            float4 v = *(const float4*)(A + (size_t)(rowBase + r) * K + k0 + aC);
            if (AMUL) {
                float4 w = *(const float4*)(A2 + (size_t)(rowBase + r) * K + k0 + aC);
                v.x *= w.x; v.y *= w.y; v.z *= w.z; v.w *= w.w;
            }
            ra[q4] = v;
        }
        #pragma unroll
        for (int q4 = 0; q4 < 4; ++q4) {
            int p = tid + q4 * 256;
            int r = p >> 5, nc = (p & 31) << 2;
            rb[q4] = *(const float4*)(Bm + (size_t)(k0 + r) * N + colBase + nc);
        }
    };
    auto stsTiles = [&](int buf) {
        #pragma unroll
        for (int q4 = 0; q4 < 4; ++q4) {
            int r = aR + q4 * 32;
            const float* e = &ra[q4].x;
            #pragma unroll
            for (int j = 0; j < 4; ++j)
                As[buf][AFRAG_W(r, aC + j, 4)] = f2tf32(e[j]);
        }
        #pragma unroll
        for (int q4 = 0; q4 < 4; ++q4) {
            int p = tid + q4 * 256;
            int k = p >> 5, nc = (p & 31) << 2;
            const float* e = &rb[q4].x;
            #pragma unroll
            for (int j = 0; j < 4; ++j)
                Bs[buf][BFRAG_W(k, nc + j, 4)] = f2tf32(e[j]);
        }
    };

    loadTiles(0);
    stsTiles(0);
    __syncthreads();

    for (int k0 = 0; k0 < K; k0 += 32) {
        const int cur = (k0 >> 5) & 1;
        const bool hasNext = (k0 + 32) < K;
        if (hasNext) loadTiles(k0 + 32);
        #pragma unroll
        for (int k8 = 0; k8 < 4; ++k8) {
            uint4 a[2];
            #pragma unroll
            for (int mt = 0; mt < 2; ++mt)
                a[mt] = *(const uint4*)&As[cur][((wr * 2 + mt) * 4 + k8) * 132 + lane * 4];
            #pragma unroll
            for (int nt = 0; nt < 8; ++nt) {
                uint2 bv = *(const uint2*)&Bs[cur][((wc * 8 + nt) * 4 + k8) * 66 + lane * 2];
                mma8(acc[0][nt], a[0].x, a[0].y, a[0].z, a[0].w, bv.x, bv.y);
                mma8(acc[1][nt], a[1].x, a[1].y, a[1].z, a[1].w, bv.x, bv.y);
            }
        }
        if (hasNext) stsTiles(cur ^ 1);
        __syncthreads();
    }

    #pragma unroll
    for (int mt = 0; mt < 2; ++mt) {
        #pragma unroll
        for (int nt = 0; nt < 8; ++nt) {
            int row = rowBase + wr * 32 + mt * 16 + lr;
            int col = colBase + wc * 64 + nt * 8 + 2 * lc;
            float b0 = bias[col], b1 = bias[col + 1];
            float2 o0, o1;
            o0.x = acc[mt][nt][0] + b0; o0.y = acc[mt][nt][1] + b1;
            o1.x = acc[mt][nt][2] + b0; o1.y = acc[mt][nt][3] + b1;
            if (SWISH) {
                o0.x = swishf(o0.x); o0.y = swishf(o0.y);
                o1.x = swishf(o1.x); o1.y = swishf(o1.y);
            }
            *(float2*)(C + (size_t)row * N + col) = o0;
            *(float2*)(C + (size_t)(row + 8) * N + col) = o1;
        }
    }
}

// =================================================================================
// Per-head projection via tf32 MMA, fragment-major, double-buffered. K = 128.
// =================================================================================
__global__ __launch_bounds__(256)
void proj_tf32(const float* __restrict__ q, const float* __restrict__ Wqkv,
               float* __restrict__ Xout)
{
    extern __shared__ uint32_t smg[];
    uint32_t* As[2] = { smg, smg + GA_WORDS };
    uint32_t* Bs[2] = { smg + 2 * GA_WORDS, smg + 2 * GA_WORDS + GB_WORDS };
    const int tid = threadIdx.x;
    const int warp = tid >> 5, lane = tid & 31;
    const int wr = warp >> 1, wc = warp & 1;
    const int lr = lane >> 2, lc = lane & 3;
    const int rowBase = blockIdx.x * 128;
    const int h = blockIdx.y;
    const float* Wh = Wqkv + (size_t)h * HD * HD;
    const int aR = tid >> 3, aC = (tid & 7) << 2;

    float acc[2][8][4];
    #pragma unroll
    for (int mt = 0; mt < 2; ++mt)
        #pragma unroll
        for (int nt = 0; nt < 8; ++nt)
            #pragma unroll
            for (int i = 0; i < 4; ++i) acc[mt][nt][i] = 0.0f;

    float4 ra[4], rb[4];
    auto loadTiles = [&](int k0) {
        #pragma unroll
        for (int q4 = 0; q4 < 4; ++q4) {
            int r = aR + q4 * 32;
            ra[q4] = *(const float4*)(q + (size_t)(rowBase + r) * DIMN + h * HD + k0 + aC);
        }
        #pragma unroll
        for (int q4 = 0; q4 < 4; ++q4) {
            int p = tid + q4 * 256;
            int r = p >> 5, nc = (p & 31) << 2;
            rb[q4] = *(const float4*)(Wh + (size_t)(k0 + r) * HD + nc);
        }
    };
    auto stsTiles = [&](int buf) {
        #pragma unroll
        for (int q4 = 0; q4 < 4; ++q4) {
            int r = aR + q4 * 32;
            const float* e = &ra[q4].x;
            #pragma unroll
            for (int j = 0; j < 4; ++j)
                As[buf][AFRAG_W(r, aC + j, 4)] = f2tf32(e[j]);
        }
        #pragma unroll
        for (int q4 = 0; q4 < 4; ++q4) {
            int p = tid + q4 * 256;
            int k = p >> 5, nc = (p & 31) << 2;
            const float* e = &rb[q4].x;
            #pragma unroll
            for (int j = 0; j < 4; ++j)
                Bs[buf][BFRAG_W(k, nc + j, 4)] = f2tf32(e[j]);
        }
    };

    loadTiles(0);
    stsTiles(0);
    __syncthreads();

    for (int k0 = 0; k0 < HD; k0 += 32) {
        const int cur = (k0 >> 5) & 1;
        const bool hasNext = (k0 + 32) < HD;
        if (hasNext) loadTiles(k0 + 32);
        #pragma unroll
        for (int k8 = 0; k8 < 4; ++k8) {
            uint4 a[2];
            #pragma unroll
            for (int mt = 0; mt < 2; ++mt)
                a[mt] = *(const uint4*)&As[cur][((wr * 2 + mt) * 4 + k8) * 132 + lane * 4];
            #pragma unroll
            for (int nt = 0; nt < 8; ++nt) {
                uint2 bv = *(const uint2*)&Bs[cur][((wc * 8 + nt) * 4 + k8) * 66 + lane * 2];
                mma8(acc[0][nt], a[0].x, a[0].y, a[0].z, a[0].w, bv.x, bv.y);
                mma8(acc[1][nt], a[1].x, a[1].y, a[1].z, a[1].w, bv.x, bv.y);
            }
        }
        if (hasNext) stsTiles(cur ^ 1);
        __syncthreads();
    }

    #pragma unroll
    for (int mt = 0; mt < 2; ++mt) {
        #pragma unroll
        for (int nt = 0; nt < 8; ++nt) {
            int i0 = rowBase + wr * 32 + mt * 16 + lr;
            int col = wc * 64 + nt * 8 + 2 * lc;
            #pragma unroll
            for (int half = 0; half < 2; ++half) {
                int i = i0 + half * 8;
                int b = i >> 11, s = i & (SEQ - 1);
                float* op = Xout + ((size_t)(b * NH + h) * SEQ + s) * HD + col;
                *(float2*)op = make_float2(acc[mt][nt][half * 2], acc[mt][nt][half * 2 + 1]);
            }
        }
    }
}

// =================================================================================
// Backward suffix scan: Sq[t] = X[t] + gamma * Sq[t+1].
// =================================================================================
__global__ void scan_kernel(float* __restrict__ Sq, const float* __restrict__ X)
{
    const int bh = blockIdx.x;
    const int h = bh & (NH - 1);
    const float gamma = 1.0f - exp2f(-5.0f - (float)h);
    const int d = blockIdx.y * 32 + threadIdx.x;
    const float* Xh = X + (size_t)bh * SEQ * HD;
    float* Sh = Sq + (size_t)bh * SEQ * HD;
    float sq = 0.0f;
    for (int t = SEQ - 1; t >= 0; --t) {
        sq = fmaf(gamma, sq, Xh[(size_t)t * HD + d]);
        Sh[(size_t)t * HD + d] = sq;
    }
}

// =================================================================================
// colscale
// =================================================================================
__global__ __launch_bounds__(256)
void colscale_kernel(float* __restrict__ colscale, const float* __restrict__ X,
                     const float* __restrict__ Sq)
{
    const int bh = blockIdx.x;
    const int h = bh & (NH - 1);
    const float gamma = 1.0f - exp2f(-5.0f - (float)h);
    const float l2g = log2f(gamma);
    const float inv1mg = exp2f(5.0f + (float)h);
    const int warp = threadIdx.x >> 5, lane = threadIdx.x & 31;
    const float inv_s = rsqrtf((float)HD);
    #pragma unroll
    for (int i = 0; i < 8; ++i) {
        int t = blockIdx.y * 64 + warp * 8 + i;
        const float* xr = X + ((size_t)bh * SEQ + t) * HD;
        const float* sr = Sq + ((size_t)bh * SEQ + t) * HD;
        float4 xv = *(const float4*)(xr + lane * 4);
        float4 sv = *(const float4*)(sr + lane * 4);
        float dot = xv.x * sv.x + xv.y * sv.y + xv.z * sv.z + xv.w * sv.w;
        #pragma unroll
        for (int o = 16; o; o >>= 1) dot += __shfl_xor_sync(0xffffffffu, dot, o);
        if (lane == 0) {
            float ct = (1.0f - exp2f((float)(SEQ - t) * l2g)) * inv1mg;
            float rs = rsqrtf(ct);
            float colsum = dot * rs * inv_s;
            colscale[(size_t)bh * SEQ + t] = rs * inv_s / fmaxf(fabsf(colsum), 1.0f);
        }
    }
}

// =================================================================================
// Retention v3: 128(q) x 64(k) tiles, fragment-major smem.
// Qf: A-frags of Q (8 mTiles x 16 k8). Kf: B-frags for scores (8 keyTiles x 16 k8).
// Vf: B-frags for AV (16 dTiles x 8 k8). Swf: A-frags of weighted scores (8 x 8).
// KV tile packed into BOTH Kf and Vf at write. Row decay in epilogue.
// =================================================================================
#define QTILE  128
#define KTILE  64
#define RQ_WORDS (128 * 132)
#define RK_WORDS (128 * 66)
#define RV_WORDS (128 * 66)
#define RS_WORDS (64 * 132)
#define RET_U32 (RQ_WORDS + RK_WORDS + RV_WORDS + RS_WORDS + KTILE + QTILE)
#define RET_SMEM (RET_U32 * 4)

__global__ __launch_bounds__(256, 1)
void retention_tf32(float* __restrict__ out, const float* __restrict__ X,
                    const float* __restrict__ colscale)
{
    extern __shared__ uint32_t sm[];
    uint32_t* Qf  = sm;
    uint32_t* Kf  = Qf + RQ_WORDS;
    uint32_t* Vf  = Kf + RK_WORDS;
    uint32_t* Swf = Vf + RV_WORDS;
    float* wcol = (float*)(Swf + RS_WORDS);
    float* powr = wcol + KTILE;

    const int sb = (int)gridDim.x - 1 - (int)blockIdx.x;   // longest blocks first
    const int bh = blockIdx.y;
    const int h = bh & (NH - 1);
    const int b = bh >> 3;
    const float gamma = 1.0f - exp2f(-5.0f - (float)h);
    const float l2g = log2f(gamma);
    const float* Xh = X + (size_t)bh * SEQ * HD;
    const float* csb = colscale + (size_t)bh * SEQ;
    const int tid = threadIdx.x;
    const int warp = tid >> 5, lane = tid & 31;
    const int wm = warp & 3, wn = warp >> 2;
    const int lr = lane >> 2, lc = lane & 3;
    const int s0 = sb * QTILE;
    const int mbase = wm * 32;
    const int jbmax = 2 * sb + 1;

    // pack one KV float4 into both Kf (scores-B) and Vf (AV-B)
    auto stKV = [&](int t, int c, float4 v) {
        const float* e = &v.x;
        #pragma unroll
        for (int j = 0; j < 4; ++j) {
            uint32_t tv = f2tf32(e[j]);
            int cc = c + j;
            Kf[BFRAG_W(cc, t, 16)] = tv;   // B element (k=dim cc, n=key t), K8CNT=16
            Vf[BFRAG_W(t, cc, 8)]  = tv;   // B element (k=key t,  n=dim cc), K8CNT=8
        }
    };

    // Q tile -> A-frag layout (once)
    #pragma unroll
    for (int i = 0; i < 16; ++i) {
        int p = tid + i * 256;
        int r = p >> 5, c = (p & 31) << 2;
        float4 v = *(const float4*)(Xh + (size_t)(s0 + r) * HD + c);
        const float* e = &v.x;
        #pragma unroll
        for (int j = 0; j < 4; ++j)
            Qf[AFRAG_W(r, c + j, 16)] = f2tf32(e[j]);
    }
    if (tid < QTILE) powr[tid] = exp2f((float)tid * l2g);
    // KV tile 0 + wcol 0
    #pragma unroll
    for (int i = 0; i < 8; ++i) {
        int p = tid + i * 256;
        int t = p >> 5, c = (p & 31) << 2;
        stKV(t, c, *(const float4*)(Xh + (size_t)t * HD + c));
    }
    if (tid < KTILE) wcol[tid] = exp2f((float)(s0 - tid) * l2g) * csb[tid];
    __syncthreads();

    float accO[2][8][4];
    #pragma unroll
    for (int mt = 0; mt < 2; ++mt)
        #pragma unroll
        for (int nt = 0; nt < 8; ++nt)
            #pragma unroll
            for (int i = 0; i < 4; ++i) accO[mt][nt][i] = 0.0f;

    for (int jb = 0; jb <= jbmax; ++jb) {
        const int t0 = jb * KTILE;
        const bool maskNeeded = (jb >= 2 * sb);
        const bool active = (s0 + mbase + 31 >= t0);

        if (active) {
            // ---- scores: S = Q @ K^T ----
            float accS[2][4][4];
            #pragma unroll
            for (int mt = 0; mt < 2; ++mt)
                #pragma unroll
                for (int nt = 0; nt < 4; ++nt)
                    #pragma unroll
                    for (int i = 0; i < 4; ++i) accS[mt][nt][i] = 0.0f;
            #pragma unroll
            for (int k8 = 0; k8 < 16; ++k8) {
                uint4 a[2];
                #pragma unroll
                for (int mt = 0; mt < 2; ++mt)
                    a[mt] = *(const uint4*)&Qf[((wm * 2 + mt) * 16 + k8) * 132 + lane * 4];
                #pragma unroll
                for (int nt = 0; nt < 4; ++nt) {
                    uint2 bv = *(const uint2*)&Kf[((wn * 4 + nt) * 16 + k8) * 66 + lane * 2];
                    mma8(accS[0][nt], a[0].x, a[0].y, a[0].z, a[0].w, bv.x, bv.y);
                    mma8(accS[1][nt], a[1].x, a[1].y, a[1].z, a[1].w, bv.x, bv.y);
                }
            }
            // stage weighted scores into Swf (A-frag layout, column factor only)
            #pragma unroll
            for (int mt = 0; mt < 2; ++mt) {
                #pragma unroll
                for (int nt = 0; nt < 4; ++nt) {
                    #pragma unroll
                    for (int v = 0; v < 4; ++v) {
                        int r  = mbase + mt * 16 + lr + (v >> 1) * 8;
                        int cK = wn * 32 + nt * 8 + 2 * lc + (v & 1);
                        float w = wcol[cK];
                        if (maskNeeded && (s0 + r < t0 + cK)) w = 0.0f;
                        Swf[AFRAG_W(r, cK, 8)] = f2tf32(accS[mt][nt][v] * w);
                    }
                }
            }
        }
        __syncthreads();   // Swf visible cross-warp

        // early global load of next KV tile (hidden under AV)
        const bool hasNext = (jb < jbmax);
        float4 nv[8];
        if (hasNext) {
            const int t0n = t0 + KTILE;
            #pragma unroll
            for (int i = 0; i < 8; ++i) {
                int p = tid + i * 256;
                int r = p >> 5, c = (p & 31) << 2;
                nv[i] = *(const float4*)(Xh + (size_t)(t0n + r) * HD + c);
            }
        }

        if (active) {
            // ---- accO += Sw @ V ----
            #pragma unroll
            for (int k8 = 0; k8 < 8; ++k8) {
                uint4 a[2];
                #pragma unroll
                for (int mt = 0; mt < 2; ++mt)
                    a[mt] = *(const uint4*)&Swf[((wm * 2 + mt) * 8 + k8) * 132 + lane * 4];
                #pragma unroll
                for (int nt = 0; nt < 8; ++nt) {
                    uint2 bv = *(const uint2*)&Vf[((wn * 8 + nt) * 8 + k8) * 66 + lane * 2];
                    mma8(accO[0][nt], a[0].x, a[0].y, a[0].z, a[0].w, bv.x, bv.y);
                    mma8(accO[1][nt], a[1].x, a[1].y, a[1].z, a[1].w, bv.x, bv.y);
                }
            }
        }
        __syncthreads();   // all reads of Kf/Vf/wcol done
        if (hasNext) {
            #pragma unroll
            for (int i = 0; i < 8; ++i) {
                int p = tid + i * 256;
                int t = p >> 5, c = (p & 31) << 2;
                stKV(t, c, nv[i]);
            }
            if (tid < KTILE) {
                int t0n = t0 + KTILE;
                wcol[tid] = exp2f((float)(s0 - t0n - tid) * l2g) * csb[t0n + tid];
            }
        }
        __syncthreads();   // new Kf/Vf/wcol visible
    }

    // epilogue: apply row decay gamma^(s - s0)
    #pragma unroll
    for (int mt = 0; mt < 2; ++mt) {
        int rl = mbase + mt * 16 + lr;
        float p0 = powr[rl], p1 = powr[rl + 8];
        int srow = s0 + rl;
        #pragma unroll
        for (int nt = 0; nt < 8; ++nt) {
            int d = wn * 64 + nt * 8 + 2 * lc;
            float* op0 = out + ((size_t)(b * SEQ + srow)) * DIMN + h * HD + d;
            float* op1 = out + ((size_t)(b * SEQ + srow + 8)) * DIMN + h * HD + d;
            *(float2*)op0 = make_float2(accO[mt][nt][0] * p0, accO[mt][nt][1] * p0);
            *(float2*)op1 = make_float2(accO[mt][nt][2] * p1, accO[mt][nt][3] * p1);
        }
    }
}

// =================================================================================
// GroupNorm: 32 groups of 32 channels, population var, eps=1e-3, + beta
// =================================================================================
__global__ __launch_bounds__(256)
void groupnorm_kernel(float* __restrict__ Y, const float* __restrict__ Xin,
                      const float* __restrict__ beta)
{
    int row = blockIdx.x >> 2;
    int gblk = blockIdx.x & 3;
    int warp = threadIdx.x >> 5, lane = threadIdx.x & 31;
    int c = gblk * 256 + warp * 32 + lane;
    float x = Xin[(size_t)row * DIMN + c];
    float s = x, s2 = x * x;
    #pragma unroll
    for (int o = 16; o; o >>= 1) {
        s  += __shfl_xor_sync(0xffffffffu, s, o);
        s2 += __shfl_xor_sync(0xffffffffu, s2, o);
    }
    float mu = s * (1.0f / 32.0f);
    float var = s2 * (1.0f / 32.0f) - mu * mu;
    float y = (x - mu) * rsqrtf(var + 1e-3f) + beta[c];
    Y[(size_t)row * DIMN + c] = y;
}

// =================================================================================
// Launch
// =================================================================================
extern "C" void kernel_launch(void* const* d_in, const int* in_sizes, int n_in,
                              void* d_out, int out_size)
{
    const float* q    = (const float*)d_in[0];
    // d_in[1] = k, d_in[2] = v : unused by the reference (retention uses q for Q,K,V)
    const float* Wqkv = (const float*)d_in[3];
    const float* Wg   = (const float*)d_in[4];
    const float* bg   = (const float*)d_in[5];
    const float* Wo   = (const float*)d_in[6];
    const float* bo   = (const float*)d_in[7];
    const float* beta = (const float*)d_in[8];
    float* out = (float*)d_out;

    float *wgate, *xy, *sr, *cscale;
    cudaGetSymbolAddress((void**)&wgate, g_wgate);
    cudaGetSymbolAddress((void**)&xy, g_xy);
    cudaGetSymbolAddress((void**)&sr, g_sr);
    cudaGetSymbolAddress((void**)&cscale, g_colscale);

    cudaFuncSetAttribute(retention_tf32, cudaFuncAttributeMaxDynamicSharedMemorySize, RET_SMEM);
    cudaFuncSetAttribute(sgemm_tf32<true, false>, cudaFuncAttributeMaxDynamicSharedMemorySize, GEMM_SMEM);
    cudaFuncSetAttribute(sgemm_tf32<false, true>, cudaFuncAttributeMaxDynamicSharedMemorySize, GEMM_SMEM);
    cudaFuncSetAttribute(proj_tf32, cudaFuncAttributeMaxDynamicSharedMemorySize, GEMM_SMEM);

    // 1. Wgate = swish(q @ Wg + bg)
    sgemm_tf32<true, false><<<dim3(DIMN / 128, MROWS / 128), 256, GEMM_SMEM>>>(q, nullptr, Wg, bg, wgate, DIMN, DIMN);
    // 2. X[b,h,s,:] = q_h @ W_qkv[h]
    proj_tf32<<<dim3(MROWS / 128, NH), 256, GEMM_SMEM>>>(q, Wqkv, xy);
    // 3. Sq suffix scan (into g_sr)
    scan_kernel<<<dim3(BATCH * NH, 4), 32>>>(sr, xy);
    // 4. per-column scale
    colscale_kernel<<<dim3(BATCH * NH, SEQ / 64), 256>>>(cscale, xy, sr);
    // 5. retention (overwrites g_sr with attention output, interleaved [row, h*128+d])
    retention_tf32<<<dim3(SEQ / QTILE, BATCH * NH), 256, RET_SMEM>>>(sr, xy, cscale);
    // 6. group norm (writes Y into g_xy)
    groupnorm_kernel<<<MROWS * 4, 256>>>(xy, sr, beta);
    // 7. out = (Wgate ⊙ Y) @ Wo + bo
    sgemm_tf32<false, true><<<dim3(DIMN / 128, MROWS / 128), 256, GEMM_SMEM>>>(wgate, xy, Wo, bo, out, DIMN, DIMN);
}

// round 15
// speedup vs baseline: 1.2859x; 1.2859x over previous
#include <cuda_runtime.h>
#include <math.h>
#include <stdint.h>

#define BATCH 4
#define SEQ   2048
#define DIMN  1024
#define NH    8
#define HD    128
#define MROWS (BATCH*SEQ)   // 8192

// ---------------- scratch (device globals; no runtime allocation) ----------------
__device__ float g_wgate[(size_t)MROWS*DIMN];          // Wgate
__device__ float g_xy[(size_t)MROWS*DIMN];             // X (per-head proj) then Y (groupnorm out)
__device__ float g_sr[(size_t)MROWS*DIMN];             // Sq (suffix scan) then retention out
__device__ float g_colscale[(size_t)BATCH*NH*SEQ];     // per-column scale

__device__ __forceinline__ float swishf(float x) { return x / (1.0f + expf(-x)); }

__device__ __forceinline__ uint32_t f2tf32(float x) {
    uint32_t y;
    asm("cvt.rna.tf32.f32 %0, %1;" : "=r"(y) : "f"(x));
    return y;
}

// D += A*B, m16n8k8 tf32, fp32 accumulate
__device__ __forceinline__ void mma8(float* d, uint32_t a0, uint32_t a1, uint32_t a2, uint32_t a3,
                                     uint32_t b0, uint32_t b1) {
    asm volatile("mma.sync.aligned.m16n8k8.row.col.f32.tf32.tf32.f32 "
                 "{%0,%1,%2,%3},{%4,%5,%6,%7},{%8,%9},{%0,%1,%2,%3};"
                 : "+f"(d[0]), "+f"(d[1]), "+f"(d[2]), "+f"(d[3])
                 : "r"(a0), "r"(a1), "r"(a2), "r"(a3), "r"(b0), "r"(b1));
}

__device__ __forceinline__ uint32_t sptr(const void* p) {
    return (uint32_t)__cvta_generic_to_shared(p);
}
// Warp-collective: 4x (8x8 b16) tiles; on b32 tiles this yields tf32 fragments.
__device__ __forceinline__ void ldsm4(uint32_t& r0, uint32_t& r1, uint32_t& r2, uint32_t& r3,
                                      uint32_t addr) {
    asm volatile("ldmatrix.sync.aligned.m8n8.x4.shared.b16 {%0,%1,%2,%3}, [%4];"
                 : "=r"(r0), "=r"(r1), "=r"(r2), "=r"(r3) : "r"(addr));
}

// =================================================================================
// TF32 tensor-core SGEMM with software-pipelined global loads (R11 832us version).
// C = epi(A (⊙A2) @ B + bias). 128x128 block, 8 warps, warp tile 32x64.
// =================================================================================
template<bool SWISH, bool AMUL>
__global__ __launch_bounds__(256)
void sgemm_tf32(const float* __restrict__ A, const float* __restrict__ A2,
                const float* __restrict__ Bm, const float* __restrict__ bias,
                float* __restrict__ C, int K, int N)
{
    __shared__ uint32_t As[128 * 36];
    __shared__ uint32_t Bs[32 * 136];
    const int tid = threadIdx.x;
    const int warp = tid >> 5, lane = tid & 31;
    const int wr = warp >> 1, wc = warp & 1;
    const int lr = lane >> 2, lc = lane & 3;
    const int rowBase = blockIdx.y * 128;
    const int colBase = blockIdx.x * 128;
    const int aR = tid >> 3, aC = (tid & 7) << 2;

    float acc[2][8][4];
    #pragma unroll
    for (int mt = 0; mt < 2; ++mt)
        #pragma unroll
        for (int nt = 0; nt < 8; ++nt)
            #pragma unroll
            for (int i = 0; i < 4; ++i) acc[mt][nt][i] = 0.0f;

    float4 ra[4], rb[4];
    auto loadTiles = [&](int k0) {
        #pragma unroll
        for (int q4 = 0; q4 < 4; ++q4) {
            int r = aR + q4 * 32;
            float4 v = *(const float4*)(A + (size_t)(rowBase + r) * K + k0 + aC);
            if (AMUL) {
                float4 w = *(const float4*)(A2 + (size_t)(rowBase + r) * K + k0 + aC);
                v.x *= w.x; v.y *= w.y; v.z *= w.z; v.w *= w.w;
            }
            ra[q4] = v;
        }
        #pragma unroll
        for (int q4 = 0; q4 < 4; ++q4) {
            int p = tid + q4 * 256;
            int r = p >> 5, nc = (p & 31) << 2;
            rb[q4] = *(const float4*)(Bm + (size_t)(k0 + r) * N + colBase + nc);
        }
    };
    auto stsTiles = [&]() {
        #pragma unroll
        for (int q4 = 0; q4 < 4; ++q4) {
            int r = aR + q4 * 32;
            uint32_t* dst = &As[r * 36 + aC];
            dst[0] = f2tf32(ra[q4].x); dst[1] = f2tf32(ra[q4].y);
            dst[2] = f2tf32(ra[q4].z); dst[3] = f2tf32(ra[q4].w);
        }
        #pragma unroll
        for (int q4 = 0; q4 < 4; ++q4) {
            int p = tid + q4 * 256;
            int r = p >> 5, nc = (p & 31) << 2;
            uint32_t* dst = &Bs[r * 136 + nc];
            dst[0] = f2tf32(rb[q4].x); dst[1] = f2tf32(rb[q4].y);
            dst[2] = f2tf32(rb[q4].z); dst[3] = f2tf32(rb[q4].w);
        }
    };

    loadTiles(0);
    stsTiles();
    __syncthreads();

    for (int k0 = 0; k0 < K; k0 += 32) {
        const bool hasNext = (k0 + 32) < K;
        if (hasNext) loadTiles(k0 + 32);     // LDG overlapped with MMA below
        #pragma unroll
        for (int k8 = 0; k8 < 4; ++k8) {
            const int kb = k8 * 8;
            uint32_t a[2][4];
            #pragma unroll
            for (int mt = 0; mt < 2; ++mt) {
                int m = wr * 32 + mt * 16;
                a[mt][0] = As[(m + lr) * 36 + kb + lc];
                a[mt][1] = As[(m + lr + 8) * 36 + kb + lc];
                a[mt][2] = As[(m + lr) * 36 + kb + lc + 4];
                a[mt][3] = As[(m + lr + 8) * 36 + kb + lc + 4];
            }
            #pragma unroll
            for (int nt = 0; nt < 8; ++nt) {
                int n = wc * 64 + nt * 8 + lr;
                uint32_t b0 = Bs[(kb + lc) * 136 + n];
                uint32_t b1 = Bs[(kb + lc + 4) * 136 + n];
                mma8(acc[0][nt], a[0][0], a[0][1], a[0][2], a[0][3], b0, b1);
                mma8(acc[1][nt], a[1][0], a[1][1], a[1][2], a[1][3], b0, b1);
            }
        }
        __syncthreads();
        if (hasNext) {
            stsTiles();
            __syncthreads();
        }
    }

    #pragma unroll
    for (int mt = 0; mt < 2; ++mt) {
        #pragma unroll
        for (int nt = 0; nt < 8; ++nt) {
            int row = rowBase + wr * 32 + mt * 16 + lr;
            int col = colBase + wc * 64 + nt * 8 + 2 * lc;
            float b0 = bias[col], b1 = bias[col + 1];
            float2 o0, o1;
            o0.x = acc[mt][nt][0] + b0; o0.y = acc[mt][nt][1] + b1;
            o1.x = acc[mt][nt][2] + b0; o1.y = acc[mt][nt][3] + b1;
            if (SWISH) {
                o0.x = swishf(o0.x); o0.y = swishf(o0.y);
                o1.x = swishf(o1.x); o1.y = swishf(o1.y);
            }
            *(float2*)(C + (size_t)row * N + col) = o0;
            *(float2*)(C + (size_t)(row + 8) * N + col) = o1;
        }
    }
}

// =================================================================================
// Per-head projection via tf32 MMA (R11 version). K = 128.
// =================================================================================
__global__ __launch_bounds__(256)
void proj_tf32(const float* __restrict__ q, const float* __restrict__ Wqkv,
               float* __restrict__ Xout)
{
    __shared__ uint32_t As[128 * 36];
    __shared__ uint32_t Bs[32 * 136];
    const int tid = threadIdx.x;
    const int warp = tid >> 5, lane = tid & 31;
    const int wr = warp >> 1, wc = warp & 1;
    const int lr = lane >> 2, lc = lane & 3;
    const int rowBase = blockIdx.x * 128;
    const int h = blockIdx.y;
    const float* Wh = Wqkv + (size_t)h * HD * HD;
    const int aR = tid >> 3, aC = (tid & 7) << 2;

    float acc[2][8][4];
    #pragma unroll
    for (int mt = 0; mt < 2; ++mt)
        #pragma unroll
        for (int nt = 0; nt < 8; ++nt)
            #pragma unroll
            for (int i = 0; i < 4; ++i) acc[mt][nt][i] = 0.0f;

    float4 ra[4], rb[4];
    auto loadTiles = [&](int k0) {
        #pragma unroll
        for (int q4 = 0; q4 < 4; ++q4) {
            int r = aR + q4 * 32;
            ra[q4] = *(const float4*)(q + (size_t)(rowBase + r) * DIMN + h * HD + k0 + aC);
        }
        #pragma unroll
        for (int q4 = 0; q4 < 4; ++q4) {
            int p = tid + q4 * 256;
            int r = p >> 5, nc = (p & 31) << 2;
            rb[q4] = *(const float4*)(Wh + (size_t)(k0 + r) * HD + nc);
        }
    };
    auto stsTiles = [&]() {
        #pragma unroll
        for (int q4 = 0; q4 < 4; ++q4) {
            int r = aR + q4 * 32;
            uint32_t* dst = &As[r * 36 + aC];
            dst[0] = f2tf32(ra[q4].x); dst[1] = f2tf32(ra[q4].y);
            dst[2] = f2tf32(ra[q4].z); dst[3] = f2tf32(ra[q4].w);
        }
        #pragma unroll
        for (int q4 = 0; q4 < 4; ++q4) {
            int p = tid + q4 * 256;
            int r = p >> 5, nc = (p & 31) << 2;
            uint32_t* dst = &Bs[r * 136 + nc];
            dst[0] = f2tf32(rb[q4].x); dst[1] = f2tf32(rb[q4].y);
            dst[2] = f2tf32(rb[q4].z); dst[3] = f2tf32(rb[q4].w);
        }
    };

    loadTiles(0);
    stsTiles();
    __syncthreads();

    for (int k0 = 0; k0 < HD; k0 += 32) {
        const bool hasNext = (k0 + 32) < HD;
        if (hasNext) loadTiles(k0 + 32);
        #pragma unroll
        for (int k8 = 0; k8 < 4; ++k8) {
            const int kb = k8 * 8;
            uint32_t a[2][4];
            #pragma unroll
            for (int mt = 0; mt < 2; ++mt) {
                int m = wr * 32 + mt * 16;
                a[mt][0] = As[(m + lr) * 36 + kb + lc];
                a[mt][1] = As[(m + lr + 8) * 36 + kb + lc];
                a[mt][2] = As[(m + lr) * 36 + kb + lc + 4];
                a[mt][3] = As[(m + lr + 8) * 36 + kb + lc + 4];
            }
            #pragma unroll
            for (int nt = 0; nt < 8; ++nt) {
                int n = wc * 64 + nt * 8 + lr;
                uint32_t b0 = Bs[(kb + lc) * 136 + n];
                uint32_t b1 = Bs[(kb + lc + 4) * 136 + n];
                mma8(acc[0][nt], a[0][0], a[0][1], a[0][2], a[0][3], b0, b1);
                mma8(acc[1][nt], a[1][0], a[1][1], a[1][2], a[1][3], b0, b1);
            }
        }
        __syncthreads();
        if (hasNext) {
            stsTiles();
            __syncthreads();
        }
    }

    #pragma unroll
    for (int mt = 0; mt < 2; ++mt) {
        #pragma unroll
        for (int nt = 0; nt < 8; ++nt) {
            int i0 = rowBase + wr * 32 + mt * 16 + lr;
            int col = wc * 64 + nt * 8 + 2 * lc;
            #pragma unroll
            for (int half = 0; half < 2; ++half) {
                int i = i0 + half * 8;
                int b = i >> 11, s = i & (SEQ - 1);
                float* op = Xout + ((size_t)(b * NH + h) * SEQ + s) * HD + col;
                *(float2*)op = make_float2(acc[mt][nt][half * 2], acc[mt][nt][half * 2 + 1]);
            }
        }
    }
}

// =================================================================================
// Backward suffix scan: Sq[t] = X[t] + gamma * Sq[t+1].
// =================================================================================
__global__ void scan_kernel(float* __restrict__ Sq, const float* __restrict__ X)
{
    const int bh = blockIdx.x;
    const int h = bh & (NH - 1);
    const float gamma = 1.0f - exp2f(-5.0f - (float)h);
    const int d = blockIdx.y * 32 + threadIdx.x;
    const float* Xh = X + (size_t)bh * SEQ * HD;
    float* Sh = Sq + (size_t)bh * SEQ * HD;
    float sq = 0.0f;
    for (int t = SEQ - 1; t >= 0; --t) {
        sq = fmaf(gamma, sq, Xh[(size_t)t * HD + d]);
        Sh[(size_t)t * HD + d] = sq;
    }
}

// =================================================================================
// colscale
// =================================================================================
__global__ __launch_bounds__(256)
void colscale_kernel(float* __restrict__ colscale, const float* __restrict__ X,
                     const float* __restrict__ Sq)
{
    const int bh = blockIdx.x;
    const int h = bh & (NH - 1);
    const float gamma = 1.0f - exp2f(-5.0f - (float)h);
    const float l2g = log2f(gamma);
    const float inv1mg = exp2f(5.0f + (float)h);
    const int warp = threadIdx.x >> 5, lane = threadIdx.x & 31;
    const float inv_s = rsqrtf((float)HD);
    #pragma unroll
    for (int i = 0; i < 8; ++i) {
        int t = blockIdx.y * 64 + warp * 8 + i;
        const float* xr = X + ((size_t)bh * SEQ + t) * HD;
        const float* sr = Sq + ((size_t)bh * SEQ + t) * HD;
        float4 xv = *(const float4*)(xr + lane * 4);
        float4 sv = *(const float4*)(sr + lane * 4);
        float dot = xv.x * sv.x + xv.y * sv.y + xv.z * sv.z + xv.w * sv.w;
        #pragma unroll
        for (int o = 16; o; o >>= 1) dot += __shfl_xor_sync(0xffffffffu, dot, o);
        if (lane == 0) {
            float ct = (1.0f - exp2f((float)(SEQ - t) * l2g)) * inv1mg;
            float rs = rsqrtf(ct);
            float colsum = dot * rs * inv_s;
            colscale[(size_t)bh * SEQ + t] = rs * inv_s / fmaxf(fabsf(colsum), 1.0f);
        }
    }
}

// =================================================================================
// Retention v4: 128(q) x 64(k) tiles, canonical row-major tiles + LDSM consumers.
// Writers keep merged STS.128; ldmatrix.x4 for score-A, score-B, AV-A fragments;
// AV-B stays scalar (conflict-free with stride 140). Row decay in epilogue.
// =================================================================================
#define QTILE  128
#define KTILE  64
#define QS_STR 140   // mod 32 = 12: LDSM 8-row fetches tile all banks; AV-B scalar also c-free
#define SW_STR 68
#define RET_U32 (QTILE*QS_STR + KTILE*QS_STR + QTILE*SW_STR + KTILE + QTILE)
#define RET_SMEM (RET_U32 * 4)

__global__ __launch_bounds__(256, 1)
void retention_tf32(float* __restrict__ out, const float* __restrict__ X,
                    const float* __restrict__ colscale)
{
    extern __shared__ uint32_t sm[];
    uint32_t* Qs  = sm;                          // 128 x 140
    uint32_t* KVs = Qs + QTILE * QS_STR;         // 64 x 140
    uint32_t* Sw  = KVs + KTILE * QS_STR;        // 128 x 68
    float* wcol = (float*)(Sw + QTILE * SW_STR); // 64
    float* powr = wcol + KTILE;                  // 128

    const int sb = (int)gridDim.x - 1 - (int)blockIdx.x;   // longest blocks first
    const int bh = blockIdx.y;
    const int h = bh & (NH - 1);
    const int b = bh >> 3;
    const float gamma = 1.0f - exp2f(-5.0f - (float)h);
    const float l2g = log2f(gamma);
    const float* Xh = X + (size_t)bh * SEQ * HD;
    const float* csb = colscale + (size_t)bh * SEQ;
    const int tid = threadIdx.x;
    const int warp = tid >> 5, lane = tid & 31;
    const int wm = warp & 3, wn = warp >> 2;
    const int lr = lane >> 2, lc = lane & 3;
    const int s0 = sb * QTILE;
    const int mbase = wm * 32;
    const int jbmax = 2 * sb + 1;

    const uint32_t qf  = sptr(Qs);
    const uint32_t kf  = sptr(KVs);
    const uint32_t swf = sptr(Sw);
    // LDSM lane addressing (A-frag): rows m..m+15, col block kb or kb+4
    const int aRowOff = lane & 15;
    const int aColOff = (lane >> 4) << 2;
    // LDSM lane addressing (B-frag pair): rows n..n+15 split, col kb / kb+4
    const int bRowOff = (lane & 7) + ((lane >> 4) << 3);
    const int bColOff = ((lane >> 3) & 1) << 2;

    // Q tile (128x128 -> tf32), merged STS.128
    #pragma unroll
    for (int i = 0; i < 16; ++i) {
        int p = tid + i * 256;
        int r = p >> 5, c4 = (p & 31) << 2;
        float4 v = *(const float4*)(Xh + (size_t)(s0 + r) * HD + c4);
        uint32_t* dst = &Qs[r * QS_STR + c4];
        dst[0] = f2tf32(v.x); dst[1] = f2tf32(v.y);
        dst[2] = f2tf32(v.z); dst[3] = f2tf32(v.w);
    }
    if (tid < QTILE) powr[tid] = exp2f((float)tid * l2g);
    // KV tile 0 + wcol 0
    #pragma unroll
    for (int i = 0; i < 8; ++i) {
        int p = tid + i * 256;
        int r = p >> 5, c4 = (p & 31) << 2;
        float4 v = *(const float4*)(Xh + (size_t)r * HD + c4);
        uint32_t* dst = &KVs[r * QS_STR + c4];
        dst[0] = f2tf32(v.x); dst[1] = f2tf32(v.y);
        dst[2] = f2tf32(v.z); dst[3] = f2tf32(v.w);
    }
    if (tid < KTILE) wcol[tid] = exp2f((float)(s0 - tid) * l2g) * csb[tid];
    __syncthreads();

    float accO[2][8][4];
    #pragma unroll
    for (int mt = 0; mt < 2; ++mt)
        #pragma unroll
        for (int nt = 0; nt < 8; ++nt)
            #pragma unroll
            for (int i = 0; i < 4; ++i) accO[mt][nt][i] = 0.0f;

    for (int jb = 0; jb <= jbmax; ++jb) {
        const int t0 = jb * KTILE;
        const bool maskNeeded = (jb >= 2 * sb);
        const bool active = (s0 + mbase + 31 >= t0);   // warp-uniform

        if (active) {
            // ---- scores: S = Q @ K^T ----
            float accS[2][4][4];
            #pragma unroll
            for (int mt = 0; mt < 2; ++mt)
                #pragma unroll
                for (int nt = 0; nt < 4; ++nt)
                    #pragma unroll
                    for (int i = 0; i < 4; ++i) accS[mt][nt][i] = 0.0f;
            #pragma unroll
            for (int k8 = 0; k8 < 16; ++k8) {
                const int kb = k8 * 8;
                uint32_t a0[4], a1[4];
                {
                    int row = mbase + aRowOff;
                    int col = kb + aColOff;
                    ldsm4(a0[0], a0[1], a0[2], a0[3], qf + (uint32_t)((row * QS_STR + col) << 2));
                    ldsm4(a1[0], a1[1], a1[2], a1[3], qf + (uint32_t)(((row + 16) * QS_STR + col) << 2));
                }
                #pragma unroll
                for (int ntp = 0; ntp < 2; ++ntp) {
                    uint32_t bb[4];
                    int rowb = wn * 32 + ntp * 16 + bRowOff;
                    int colb = kb + bColOff;
                    ldsm4(bb[0], bb[1], bb[2], bb[3], kf + (uint32_t)((rowb * QS_STR + colb) << 2));
                    mma8(accS[0][2 * ntp],     a0[0], a0[1], a0[2], a0[3], bb[0], bb[1]);
                    mma8(accS[1][2 * ntp],     a1[0], a1[1], a1[2], a1[3], bb[0], bb[1]);
                    mma8(accS[0][2 * ntp + 1], a0[0], a0[1], a0[2], a0[3], bb[2], bb[3]);
                    mma8(accS[1][2 * ntp + 1], a1[0], a1[1], a1[2], a1[3], bb[2], bb[3]);
                }
            }
            // stage weighted scores (column factor only; row factor in epilogue)
            #pragma unroll
            for (int mt = 0; mt < 2; ++mt) {
                #pragma unroll
                for (int nt = 0; nt < 4; ++nt) {
                    #pragma unroll
                    for (int half = 0; half < 2; ++half) {
                        int rl = mbase + mt * 16 + lr + half * 8;
                        #pragma unroll
                        for (int e = 0; e < 2; ++e) {
                            int cl = wn * 32 + nt * 8 + 2 * lc + e;
                            float w = wcol[cl];
                            if (maskNeeded && (s0 + rl < t0 + cl)) w = 0.0f;
                            Sw[rl * SW_STR + cl] = f2tf32(accS[mt][nt][half * 2 + e] * w);
                        }
                    }
                }
            }
        }
        __syncthreads();   // Sw visible cross-warp (AV reads full 64-key columns)

        // early global load of next KV tile (hidden under AV)
        const bool hasNext = (jb < jbmax);
        float4 nv[8];
        if (hasNext) {
            const int t0n = t0 + KTILE;
            #pragma unroll
            for (int i = 0; i < 8; ++i) {
                int p = tid + i * 256;
                int r = p >> 5, c = (p & 31) << 2;
                nv[i] = *(const float4*)(Xh + (size_t)(t0n + r) * HD + c);
            }
        }

        if (active) {
            // ---- accO += Sw @ V ----
            #pragma unroll
            for (int k8 = 0; k8 < 8; ++k8) {
                const int kb = k8 * 8;
                uint32_t a0[4], a1[4];
                {
                    int row = mbase + aRowOff;
                    int col = kb + aColOff;
                    ldsm4(a0[0], a0[1], a0[2], a0[3], swf + (uint32_t)((row * SW_STR + col) << 2));
                    ldsm4(a1[0], a1[1], a1[2], a1[3], swf + (uint32_t)(((row + 16) * SW_STR + col) << 2));
                }
                #pragma unroll
                for (int nt = 0; nt < 8; ++nt) {
                    int n = wn * 64 + nt * 8 + lr;
                    uint32_t b0 = KVs[(kb + lc) * QS_STR + n];
                    uint32_t b1 = KVs[(kb + lc + 4) * QS_STR + n];
                    mma8(accO[0][nt], a0[0], a0[1], a0[2], a0[3], b0, b1);
                    mma8(accO[1][nt], a1[0], a1[1], a1[2], a1[3], b0, b1);
                }
            }
        }
        __syncthreads();   // all reads of KVs/wcol done
        if (hasNext) {
            #pragma unroll
            for (int i = 0; i < 8; ++i) {
                int p = tid + i * 256;
                int r = p >> 5, c4 = (p & 31) << 2;
                uint32_t* dst = &KVs[r * QS_STR + c4];
                dst[0] = f2tf32(nv[i].x); dst[1] = f2tf32(nv[i].y);
                dst[2] = f2tf32(nv[i].z); dst[3] = f2tf32(nv[i].w);
            }
            if (tid < KTILE) {
                int t0n = t0 + KTILE;
                wcol[tid] = exp2f((float)(s0 - t0n - tid) * l2g) * csb[t0n + tid];
            }
        }
        __syncthreads();   // new KVs/wcol visible for next iteration
    }

    // epilogue: apply row decay gamma^(s - s0)
    #pragma unroll
    for (int mt = 0; mt < 2; ++mt) {
        int rl = mbase + mt * 16 + lr;
        float p0 = powr[rl], p1 = powr[rl + 8];
        int srow = s0 + rl;
        #pragma unroll
        for (int nt = 0; nt < 8; ++nt) {
            int d = wn * 64 + nt * 8 + 2 * lc;
            float* op0 = out + ((size_t)(b * SEQ + srow)) * DIMN + h * HD + d;
            float* op1 = out + ((size_t)(b * SEQ + srow + 8)) * DIMN + h * HD + d;
            *(float2*)op0 = make_float2(accO[mt][nt][0] * p0, accO[mt][nt][1] * p0);
            *(float2*)op1 = make_float2(accO[mt][nt][2] * p1, accO[mt][nt][3] * p1);
        }
    }
}

// =================================================================================
// GroupNorm: 32 groups of 32 channels, population var, eps=1e-3, + beta
// =================================================================================
__global__ __launch_bounds__(256)
void groupnorm_kernel(float* __restrict__ Y, const float* __restrict__ Xin,
                      const float* __restrict__ beta)
{
    int row = blockIdx.x >> 2;
    int gblk = blockIdx.x & 3;
    int warp = threadIdx.x >> 5, lane = threadIdx.x & 31;
    int c = gblk * 256 + warp * 32 + lane;
    float x = Xin[(size_t)row * DIMN + c];
    float s = x, s2 = x * x;
    #pragma unroll
    for (int o = 16; o; o >>= 1) {
        s  += __shfl_xor_sync(0xffffffffu, s, o);
        s2 += __shfl_xor_sync(0xffffffffu, s2, o);
    }
    float mu = s * (1.0f / 32.0f);
    float var = s2 * (1.0f / 32.0f) - mu * mu;
    float y = (x - mu) * rsqrtf(var + 1e-3f) + beta[c];
    Y[(size_t)row * DIMN + c] = y;
}

// =================================================================================
// Launch
// =================================================================================
extern "C" void kernel_launch(void* const* d_in, const int* in_sizes, int n_in,
                              void* d_out, int out_size)
{
    const float* q    = (const float*)d_in[0];
    // d_in[1] = k, d_in[2] = v : unused by the reference (retention uses q for Q,K,V)
    const float* Wqkv = (const float*)d_in[3];
    const float* Wg   = (const float*)d_in[4];
    const float* bg   = (const float*)d_in[5];
    const float* Wo   = (const float*)d_in[6];
    const float* bo   = (const float*)d_in[7];
    const float* beta = (const float*)d_in[8];
    float* out = (float*)d_out;

    float *wgate, *xy, *sr, *cscale;
    cudaGetSymbolAddress((void**)&wgate, g_wgate);
    cudaGetSymbolAddress((void**)&xy, g_xy);
    cudaGetSymbolAddress((void**)&sr, g_sr);
    cudaGetSymbolAddress((void**)&cscale, g_colscale);

    cudaFuncSetAttribute(retention_tf32, cudaFuncAttributeMaxDynamicSharedMemorySize, RET_SMEM);

    // 1. Wgate = swish(q @ Wg + bg)
    sgemm_tf32<true, false><<<dim3(DIMN / 128, MROWS / 128), 256>>>(q, nullptr, Wg, bg, wgate, DIMN, DIMN);
    // 2. X[b,h,s,:] = q_h @ W_qkv[h]
    proj_tf32<<<dim3(MROWS / 128, NH), 256>>>(q, Wqkv, xy);
    // 3. Sq suffix scan (into g_sr)
    scan_kernel<<<dim3(BATCH * NH, 4), 32>>>(sr, xy);
    // 4. per-column scale
    colscale_kernel<<<dim3(BATCH * NH, SEQ / 64), 256>>>(cscale, xy, sr);
    // 5. retention (overwrites g_sr with attention output, interleaved [row, h*128+d])
    retention_tf32<<<dim3(SEQ / QTILE, BATCH * NH), 256, RET_SMEM>>>(sr, xy, cscale);
    // 6. group norm (writes Y into g_xy)
    groupnorm_kernel<<<MROWS * 4, 256>>>(xy, sr, beta);
    // 7. out = (Wgate ⊙ Y) @ Wo + bo
    sgemm_tf32<false, true><<<dim3(DIMN / 128, MROWS / 128), 256>>>(wgate, xy, Wo, bo, out, DIMN, DIMN);
}